// round 1
// baseline (speedup 1.0000x reference)
#include <cuda_runtime.h>

#define NB 4
#define NH 16
#define LSEQ 2048
#define HDIM 64
#define DMODEL 1024
#define M_TOT (NB*LSEQ)            // 8192
#define OUT_ELEMS (M_TOT*DMODEL)   // 8388608
#define SQS (64*68)                // one 64x64 tile with stride 68

// Scratch (device globals; no allocation allowed)
__device__ float g_q[NB*NH*LSEQ*HDIM];
__device__ float g_k[NB*NH*LSEQ*HDIM];
__device__ float g_v[NB*NH*LSEQ*HDIM];
__device__ float g_o[NB*NH*LSEQ*HDIM];
__device__ float g_m[NB*NH*LSEQ];
__device__ float g_s[NB*NH*LSEQ];

// ---------------------------------------------------------------------------
// Tiled fp32 GEMM: C[m,n] = sum_k A[m,k] * W[n,k] (+ bias[n])
// BM=128, BN=64, BK=16, 256 threads, 8x4 per thread.
// gatherA: A is read from head-split layout [B,H,L,HD] (for output projection)
// scatterC: C is written to head-split layout (for Q/K/V projections)
// ---------------------------------------------------------------------------
__global__ __launch_bounds__(256) void gemm_kernel(
    const float* __restrict__ A, const float* __restrict__ W,
    const float* __restrict__ bias, float* __restrict__ C,
    int gatherA, int scatterC)
{
    __shared__ float As[16 * 132];   // [k][m], stride 132 (16B aligned rows)
    __shared__ float Bs[16 * 68];    // [k][n], stride 68

    const int tid = threadIdx.x;
    const int m0 = blockIdx.y * 128;
    const int n0 = blockIdx.x * 64;
    const int tx = tid & 15;         // 16 col groups of 4
    const int ty = tid >> 4;         // 16 row groups of 8

    float acc[8][4];
#pragma unroll
    for (int i = 0; i < 8; i++)
#pragma unroll
        for (int j = 0; j < 4; j++) acc[i][j] = 0.f;

    for (int k0 = 0; k0 < DMODEL; k0 += 16) {
        // --- load A tile (128 x 16), transposed into As[k][m] ---
#pragma unroll
        for (int i = 0; i < 2; i++) {
            int idx = tid + i * 256;
            int r = idx >> 2;
            int c4 = (idx & 3) << 2;
            int m = m0 + r;
            const float* src;
            if (!gatherA) {
                src = A + (size_t)m * DMODEL + k0 + c4;
            } else {
                int k = k0 + c4;
                // A[m,k] = g_o[((b*NH + h)*LSEQ + l)*HDIM + hd]
                src = A + (((size_t)((m >> 11) * NH + (k >> 6)) * LSEQ + (m & 2047)) * HDIM)
                        + (k & 63);
            }
            float4 v = *(const float4*)src;
            As[(c4 + 0) * 132 + r] = v.x;
            As[(c4 + 1) * 132 + r] = v.y;
            As[(c4 + 2) * 132 + r] = v.z;
            As[(c4 + 3) * 132 + r] = v.w;
        }
        // --- load W tile (64 x 16), transposed into Bs[k][n] ---
        {
            int r = tid >> 2;
            int c4 = (tid & 3) << 2;
            float4 v = *(const float4*)(W + (size_t)(n0 + r) * DMODEL + k0 + c4);
            Bs[(c4 + 0) * 68 + r] = v.x;
            Bs[(c4 + 1) * 68 + r] = v.y;
            Bs[(c4 + 2) * 68 + r] = v.z;
            Bs[(c4 + 3) * 68 + r] = v.w;
        }
        __syncthreads();

        // fresh sub-accumulator per 16-k tile (reduces accumulation error)
        float tacc[8][4];
#pragma unroll
        for (int i = 0; i < 8; i++)
#pragma unroll
            for (int j = 0; j < 4; j++) tacc[i][j] = 0.f;

#pragma unroll
        for (int k = 0; k < 16; k++) {
            float4 a0 = *(const float4*)&As[k * 132 + ty * 8];
            float4 a1 = *(const float4*)&As[k * 132 + ty * 8 + 4];
            float4 b  = *(const float4*)&Bs[k * 68 + tx * 4];
            float av[8] = {a0.x, a0.y, a0.z, a0.w, a1.x, a1.y, a1.z, a1.w};
            float bv[4] = {b.x, b.y, b.z, b.w};
#pragma unroll
            for (int i = 0; i < 8; i++)
#pragma unroll
                for (int j = 0; j < 4; j++) tacc[i][j] += av[i] * bv[j];
        }
#pragma unroll
        for (int i = 0; i < 8; i++)
#pragma unroll
            for (int j = 0; j < 4; j++) acc[i][j] += tacc[i][j];
        __syncthreads();
    }

    float bv[4] = {0.f, 0.f, 0.f, 0.f};
    if (bias) {
#pragma unroll
        for (int j = 0; j < 4; j++) bv[j] = bias[n0 + tx * 4 + j];
    }
#pragma unroll
    for (int i = 0; i < 8; i++) {
        int m = m0 + ty * 8 + i;
        float4 o = make_float4(acc[i][0] + bv[0], acc[i][1] + bv[1],
                               acc[i][2] + bv[2], acc[i][3] + bv[3]);
        float* dst;
        if (scatterC) {
            int h = n0 >> 6;  // BN==HDIM: one head per n-tile
            dst = C + (((size_t)((m >> 11) * NH + h) * LSEQ + (m & 2047)) * HDIM) + tx * 4;
        } else {
            dst = C + (size_t)m * DMODEL + n0 + tx * 4;
        }
        *(float4*)dst = o;
    }
}

// ---------------------------------------------------------------------------
// Flash-attention (fp32): per CTA one (b,h) and one 64-row Q block.
// K stored d-major (transposed) in smem -> conflict-free float4 LDS.
// ---------------------------------------------------------------------------
__global__ __launch_bounds__(256) void flash_kernel()
{
    extern __shared__ float sm[];
    float* Qs   = sm;              // [r][d], stride 68
    float* Kt   = sm + SQS;        // [d][t], stride 68
    float* Vs   = sm + 2 * SQS;    // [t][d], stride 68
    float* Ps   = sm + 3 * SQS;    // [r][t], stride 68
    float* mrow = sm + 4 * SQS;    // 64
    float* srow = mrow + 64;       // 64
    float* crow = srow + 64;       // 64

    const int tid = threadIdx.x;
    const int bh  = blockIdx.y;
    const int r0  = blockIdx.x * 64;
    const float scale = 0.125f;    // 1/sqrt(64)
    const float NEG_INF = __int_as_float(0xff800000u);

    const float* Qg = g_q + (size_t)bh * (LSEQ * HDIM);
    const float* Kg = g_k + (size_t)bh * (LSEQ * HDIM);
    const float* Vg = g_v + (size_t)bh * (LSEQ * HDIM);

#pragma unroll
    for (int i = 0; i < 4; i++) {
        int idx = tid + i * 256;
        int r = idx >> 4;
        int d4 = (idx & 15) << 2;
        *(float4*)&Qs[r * 68 + d4] = *(const float4*)(Qg + (size_t)(r0 + r) * HDIM + d4);
    }
    if (tid < 64) { mrow[tid] = NEG_INF; srow[tid] = 0.f; }

    const int ro = (tid >> 4) * 4;
    const int co = (tid & 15) * 4;
    float acc[4][4];
#pragma unroll
    for (int i = 0; i < 4; i++)
#pragma unroll
        for (int j = 0; j < 4; j++) acc[i][j] = 0.f;

    for (int t0 = 0; t0 < LSEQ; t0 += 64) {
        __syncthreads();  // protect prior-iter smem reads (also covers Q/stats init)
        // load K (transposed) and V tiles
#pragma unroll
        for (int i = 0; i < 4; i++) {
            int idx = tid + i * 256;
            int t = idx >> 4;
            int d4 = (idx & 15) << 2;
            float4 kv = *(const float4*)(Kg + (size_t)(t0 + t) * HDIM + d4);
            Kt[(d4 + 0) * 68 + t] = kv.x;
            Kt[(d4 + 1) * 68 + t] = kv.y;
            Kt[(d4 + 2) * 68 + t] = kv.z;
            Kt[(d4 + 3) * 68 + t] = kv.w;
            *(float4*)&Vs[t * 68 + d4] = *(const float4*)(Vg + (size_t)(t0 + t) * HDIM + d4);
        }
        __syncthreads();

        // S = Q K^T (64x64), 4x4 per thread
        float sacc[4][4];
#pragma unroll
        for (int i = 0; i < 4; i++)
#pragma unroll
            for (int j = 0; j < 4; j++) sacc[i][j] = 0.f;
#pragma unroll 16
        for (int d = 0; d < 64; d++) {
            float4 kv = *(const float4*)&Kt[d * 68 + co];
            float q0 = Qs[(ro + 0) * 68 + d];
            float q1 = Qs[(ro + 1) * 68 + d];
            float q2 = Qs[(ro + 2) * 68 + d];
            float q3 = Qs[(ro + 3) * 68 + d];
            sacc[0][0] += q0 * kv.x; sacc[0][1] += q0 * kv.y; sacc[0][2] += q0 * kv.z; sacc[0][3] += q0 * kv.w;
            sacc[1][0] += q1 * kv.x; sacc[1][1] += q1 * kv.y; sacc[1][2] += q1 * kv.z; sacc[1][3] += q1 * kv.w;
            sacc[2][0] += q2 * kv.x; sacc[2][1] += q2 * kv.y; sacc[2][2] += q2 * kv.z; sacc[2][3] += q2 * kv.w;
            sacc[3][0] += q3 * kv.x; sacc[3][1] += q3 * kv.y; sacc[3][2] += q3 * kv.z; sacc[3][3] += q3 * kv.w;
        }
#pragma unroll
        for (int i = 0; i < 4; i++) {
            *(float4*)&Ps[(ro + i) * 68 + co] =
                make_float4(sacc[i][0] * scale, sacc[i][1] * scale,
                            sacc[i][2] * scale, sacc[i][3] * scale);
        }
        __syncthreads();

        // row stats: 4 threads per row
        {
            int row = tid >> 2, seg = tid & 3;
            float mx = NEG_INF;
#pragma unroll
            for (int c = 0; c < 16; c++) mx = fmaxf(mx, Ps[row * 68 + seg * 16 + c]);
            mx = fmaxf(mx, __shfl_xor_sync(0xffffffffu, mx, 1));
            mx = fmaxf(mx, __shfl_xor_sync(0xffffffffu, mx, 2));
            if (seg == 0) {
                float mo = mrow[row];
                float mn = fmaxf(mo, mx);
                crow[row] = __expf(mo - mn);
                mrow[row] = mn;
            }
        }
        __syncthreads();

        // P = exp(S - m), accumulate row sums
        {
            int row = tid >> 2, seg = tid & 3;
            float mn = mrow[row];
            float sum = 0.f;
#pragma unroll
            for (int c = 0; c < 16; c++) {
                float p = __expf(Ps[row * 68 + seg * 16 + c] - mn);
                Ps[row * 68 + seg * 16 + c] = p;
                sum += p;
            }
            sum += __shfl_xor_sync(0xffffffffu, sum, 1);
            sum += __shfl_xor_sync(0xffffffffu, sum, 2);
            if (seg == 0) srow[row] = srow[row] * crow[row] + sum;
        }
        __syncthreads();

        // rescale O and accumulate P @ V
        float c0 = crow[ro + 0], c1 = crow[ro + 1], c2 = crow[ro + 2], c3 = crow[ro + 3];
#pragma unroll
        for (int j = 0; j < 4; j++) {
            acc[0][j] *= c0; acc[1][j] *= c1; acc[2][j] *= c2; acc[3][j] *= c3;
        }
#pragma unroll 16
        for (int t = 0; t < 64; t++) {
            float4 v = *(const float4*)&Vs[t * 68 + co];
            float p0 = Ps[(ro + 0) * 68 + t];
            float p1 = Ps[(ro + 1) * 68 + t];
            float p2 = Ps[(ro + 2) * 68 + t];
            float p3 = Ps[(ro + 3) * 68 + t];
            acc[0][0] += p0 * v.x; acc[0][1] += p0 * v.y; acc[0][2] += p0 * v.z; acc[0][3] += p0 * v.w;
            acc[1][0] += p1 * v.x; acc[1][1] += p1 * v.y; acc[1][2] += p1 * v.z; acc[1][3] += p1 * v.w;
            acc[2][0] += p2 * v.x; acc[2][1] += p2 * v.y; acc[2][2] += p2 * v.z; acc[2][3] += p2 * v.w;
            acc[3][0] += p3 * v.x; acc[3][1] += p3 * v.y; acc[3][2] += p3 * v.z; acc[3][3] += p3 * v.w;
        }
    }

    float* Og = g_o + (size_t)bh * (LSEQ * HDIM);
#pragma unroll
    for (int i = 0; i < 4; i++) {
        float inv = 1.0f / srow[ro + i];
        *(float4*)(Og + (size_t)(r0 + ro + i) * HDIM + co) =
            make_float4(acc[i][0] * inv, acc[i][1] * inv, acc[i][2] * inv, acc[i][3] * inv);
    }
    if (tid < 64) {
        g_m[(size_t)bh * LSEQ + r0 + tid] = mrow[tid];
        g_s[(size_t)bh * LSEQ + r0 + tid] = srow[tid];
    }
}

// ---------------------------------------------------------------------------
// Attention-matrix writer (only when out_size includes attention):
// recompute S tilewise, apply stored (m, s), write [B,H,L,T] fp32.
// ---------------------------------------------------------------------------
__global__ __launch_bounds__(256) void attnout_kernel(float* __restrict__ att)
{
    __shared__ float Qs[SQS];
    __shared__ float Kt[SQS];
    __shared__ float mrow[64];
    __shared__ float sinv[64];

    const int tid = threadIdx.x;
    const int bh  = blockIdx.y;
    const int r0  = blockIdx.x * 64;
    const float scale = 0.125f;

    const float* Qg = g_q + (size_t)bh * (LSEQ * HDIM);
    const float* Kg = g_k + (size_t)bh * (LSEQ * HDIM);

#pragma unroll
    for (int i = 0; i < 4; i++) {
        int idx = tid + i * 256;
        int r = idx >> 4;
        int d4 = (idx & 15) << 2;
        *(float4*)&Qs[r * 68 + d4] = *(const float4*)(Qg + (size_t)(r0 + r) * HDIM + d4);
    }
    if (tid < 64) {
        mrow[tid] = g_m[(size_t)bh * LSEQ + r0 + tid];
        sinv[tid] = 1.0f / g_s[(size_t)bh * LSEQ + r0 + tid];
    }

    const int ro = (tid >> 4) * 4;
    const int co = (tid & 15) * 4;

    for (int t0 = 0; t0 < LSEQ; t0 += 64) {
        __syncthreads();  // covers init loads and prior-iter Kt reads
#pragma unroll
        for (int i = 0; i < 4; i++) {
            int idx = tid + i * 256;
            int t = idx >> 4;
            int d4 = (idx & 15) << 2;
            float4 kv = *(const float4*)(Kg + (size_t)(t0 + t) * HDIM + d4);
            Kt[(d4 + 0) * 68 + t] = kv.x;
            Kt[(d4 + 1) * 68 + t] = kv.y;
            Kt[(d4 + 2) * 68 + t] = kv.z;
            Kt[(d4 + 3) * 68 + t] = kv.w;
        }
        __syncthreads();

        float sacc[4][4];
#pragma unroll
        for (int i = 0; i < 4; i++)
#pragma unroll
            for (int j = 0; j < 4; j++) sacc[i][j] = 0.f;
#pragma unroll 16
        for (int d = 0; d < 64; d++) {
            float4 kv = *(const float4*)&Kt[d * 68 + co];
            float q0 = Qs[(ro + 0) * 68 + d];
            float q1 = Qs[(ro + 1) * 68 + d];
            float q2 = Qs[(ro + 2) * 68 + d];
            float q3 = Qs[(ro + 3) * 68 + d];
            sacc[0][0] += q0 * kv.x; sacc[0][1] += q0 * kv.y; sacc[0][2] += q0 * kv.z; sacc[0][3] += q0 * kv.w;
            sacc[1][0] += q1 * kv.x; sacc[1][1] += q1 * kv.y; sacc[1][2] += q1 * kv.z; sacc[1][3] += q1 * kv.w;
            sacc[2][0] += q2 * kv.x; sacc[2][1] += q2 * kv.y; sacc[2][2] += q2 * kv.z; sacc[2][3] += q2 * kv.w;
            sacc[3][0] += q3 * kv.x; sacc[3][1] += q3 * kv.y; sacc[3][2] += q3 * kv.z; sacc[3][3] += q3 * kv.w;
        }
#pragma unroll
        for (int i = 0; i < 4; i++) {
            float mi = mrow[ro + i];
            float si = sinv[ro + i];
            float4 o = make_float4(__expf(sacc[i][0] * scale - mi) * si,
                                   __expf(sacc[i][1] * scale - mi) * si,
                                   __expf(sacc[i][2] * scale - mi) * si,
                                   __expf(sacc[i][3] * scale - mi) * si);
            *(float4*)(att + ((size_t)bh * LSEQ + r0 + ro + i) * LSEQ + t0 + co) = o;
        }
    }
}

// ---------------------------------------------------------------------------
extern "C" void kernel_launch(void* const* d_in, const int* in_sizes, int n_in,
                              void* d_out, int out_size)
{
    const float* query = (const float*)d_in[0];
    const float* key   = (const float*)d_in[1];
    const float* value = (const float*)d_in[2];
    const float* Wq    = (const float*)d_in[3];
    const float* Wk    = (const float*)d_in[4];
    const float* Wv    = (const float*)d_in[5];
    const float* Wo    = (const float*)d_in[6];
    const float* bo    = (const float*)d_in[7];
    float* out = (float*)d_out;

    float *qp, *kp, *vp, *op;
    cudaGetSymbolAddress((void**)&qp, g_q);
    cudaGetSymbolAddress((void**)&kp, g_k);
    cudaGetSymbolAddress((void**)&vp, g_v);
    cudaGetSymbolAddress((void**)&op, g_o);

    dim3 gemm_grid(DMODEL / 64, M_TOT / 128);
    gemm_kernel<<<gemm_grid, 256>>>(query, Wq, nullptr, qp, 0, 1);
    gemm_kernel<<<gemm_grid, 256>>>(key,   Wk, nullptr, kp, 0, 1);
    gemm_kernel<<<gemm_grid, 256>>>(value, Wv, nullptr, vp, 0, 1);

    int shm = (4 * SQS + 192) * (int)sizeof(float);  // 70400 bytes
    cudaFuncSetAttribute(flash_kernel, cudaFuncAttributeMaxDynamicSharedMemorySize, shm);
    flash_kernel<<<dim3(LSEQ / 64, NB * NH), 256, shm>>>();

    gemm_kernel<<<gemm_grid, 256>>>(op, Wo, bo, out, 1, 0);

    if (out_size > OUT_ELEMS) {
        attnout_kernel<<<dim3(LSEQ / 64, NB * NH), 256>>>(out + OUT_ELEMS);
    }
}

// round 5
// speedup vs baseline: 1.0143x; 1.0143x over previous
#include <cuda_runtime.h>
#include <cstdint>

#define NB 4
#define NH 16
#define LSEQ 2048
#define HDIM 64
#define DMODEL 1024
#define M_TOT (NB*LSEQ)            // 8192
#define OUT_ELEMS (M_TOT*DMODEL)   // 8388608
#define SQS (64*68)

// GEMM tiling: BM=128, BN=128, BK=32, 256 threads, 8x8/thread, double-buffered
#define GBK 32
#define GNCHUNK (DMODEL/GBK)       // 32
#define G_TILE_F (GBK*132)         // floats per (A or B) buffer: 4224
#define G_SMEM_B (4*G_TILE_F*4)    // 2 bufs x (A+B) = 67584 bytes

// Scratch (device globals; no allocation allowed)
__device__ float g_q[NB*NH*LSEQ*HDIM];
__device__ float g_k[NB*NH*LSEQ*HDIM];
__device__ float g_v[NB*NH*LSEQ*HDIM];
__device__ float g_o[NB*NH*LSEQ*HDIM];
__device__ float g_m[NB*NH*LSEQ];
__device__ float g_s[NB*NH*LSEQ];

// ===========================================================================
// SIMT GEMM v2: C[m,n] = sum_k A[m,k] * W[n,k] (+ bias[n])
// 128x128 tile, BK=32, 256 threads, 8x8 per thread, double-buffered smem.
// gatherA: A read from head-split [B,H,L,HD]; scatterC: C written head-split.
// ===========================================================================
__global__ __launch_bounds__(256) void gemm2(
    const float* __restrict__ A, const float* __restrict__ W,
    const float* __restrict__ bias, float* __restrict__ C,
    int gatherA, int scatterC)
{
    extern __shared__ float gsm[];
    // layout: As[buf] = gsm + buf*G_TILE_F ; Bs[buf] = gsm + 2*G_TILE_F + buf*G_TILE_F
    const int tid = threadIdx.x;
    const int tx = tid & 15;         // n groups of 8
    const int ty = tid >> 4;         // m groups of 8
    const int m0 = blockIdx.y * 128;
    const int n0 = blockIdx.x * 128;

    // per-thread load coords (4 float4 each for A and B per chunk)
    const int lr  = tid >> 3;            // row 0..31 base; +32 per i
    const int lc4 = (tid & 7) << 2;      // k offset 0,4,...,28

    float acc[8][8];
#pragma unroll
    for (int i = 0; i < 8; i++)
#pragma unroll
        for (int j = 0; j < 8; j++) acc[i][j] = 0.f;

    float4 ra[4], rb[4];

    // ---- load chunk 0 into regs ----
#pragma unroll
    for (int i = 0; i < 4; i++) {
        int r = lr + i * 32;
        if (!gatherA) {
            ra[i] = *(const float4*)(A + (size_t)(m0 + r) * DMODEL + lc4);
        } else {
            int m = m0 + r, k = lc4;
            ra[i] = *(const float4*)(A +
                (((size_t)((m >> 11) * NH + (k >> 6)) * LSEQ + (m & 2047)) * HDIM) + (k & 63));
        }
        rb[i] = *(const float4*)(W + (size_t)(n0 + r) * DMODEL + lc4);
    }

    for (int c = 0; c < GNCHUNK; c++) {
        const int buf = c & 1;
        float* As = gsm + buf * G_TILE_F;
        float* Bs = gsm + 2 * G_TILE_F + buf * G_TILE_F;

        // ---- store regs (chunk c) to smem buf ----
#pragma unroll
        for (int i = 0; i < 4; i++) {
            int r = lr + i * 32;
            As[(lc4 + 0) * 132 + r] = ra[i].x;
            As[(lc4 + 1) * 132 + r] = ra[i].y;
            As[(lc4 + 2) * 132 + r] = ra[i].z;
            As[(lc4 + 3) * 132 + r] = ra[i].w;
            Bs[(lc4 + 0) * 132 + r] = rb[i].x;
            Bs[(lc4 + 1) * 132 + r] = rb[i].y;
            Bs[(lc4 + 2) * 132 + r] = rb[i].z;
            Bs[(lc4 + 3) * 132 + r] = rb[i].w;
        }
        __syncthreads();

        // ---- prefetch chunk c+1 into regs (hidden under compute) ----
        if (c + 1 < GNCHUNK) {
            int k0 = (c + 1) * GBK;
#pragma unroll
            for (int i = 0; i < 4; i++) {
                int r = lr + i * 32;
                if (!gatherA) {
                    ra[i] = *(const float4*)(A + (size_t)(m0 + r) * DMODEL + k0 + lc4);
                } else {
                    int m = m0 + r, k = k0 + lc4;
                    ra[i] = *(const float4*)(A +
                        (((size_t)((m >> 11) * NH + (k >> 6)) * LSEQ + (m & 2047)) * HDIM) + (k & 63));
                }
                rb[i] = *(const float4*)(W + (size_t)(n0 + r) * DMODEL + k0 + lc4);
            }
        }

        // ---- compute chunk c: fresh sub-accumulator (bounded rounding chains) ----
        float tacc[8][8];
#pragma unroll
        for (int i = 0; i < 8; i++)
#pragma unroll
            for (int j = 0; j < 8; j++) tacc[i][j] = 0.f;

#pragma unroll
        for (int k = 0; k < GBK; k++) {
            float4 a0 = *(const float4*)&As[k * 132 + ty * 8];
            float4 a1 = *(const float4*)&As[k * 132 + ty * 8 + 4];
            float4 b0 = *(const float4*)&Bs[k * 132 + tx * 8];
            float4 b1 = *(const float4*)&Bs[k * 132 + tx * 8 + 4];
            float av[8] = {a0.x, a0.y, a0.z, a0.w, a1.x, a1.y, a1.z, a1.w};
            float bv[8] = {b0.x, b0.y, b0.z, b0.w, b1.x, b1.y, b1.z, b1.w};
#pragma unroll
            for (int i = 0; i < 8; i++)
#pragma unroll
                for (int j = 0; j < 8; j++) tacc[i][j] += av[i] * bv[j];
        }
#pragma unroll
        for (int i = 0; i < 8; i++)
#pragma unroll
            for (int j = 0; j < 8; j++) acc[i][j] += tacc[i][j];

        __syncthreads();  // all done reading buf before it is overwritten next iter
    }

    // ---- epilogue ----
    float bv[8] = {0, 0, 0, 0, 0, 0, 0, 0};
    if (bias) {
        float4 b0 = *(const float4*)(bias + n0 + tx * 8);
        float4 b1 = *(const float4*)(bias + n0 + tx * 8 + 4);
        bv[0] = b0.x; bv[1] = b0.y; bv[2] = b0.z; bv[3] = b0.w;
        bv[4] = b1.x; bv[5] = b1.y; bv[6] = b1.z; bv[7] = b1.w;
    }
#pragma unroll
    for (int i = 0; i < 8; i++) {
        int m = m0 + ty * 8 + i;
#pragma unroll
        for (int jj = 0; jj < 2; jj++) {
            int n = n0 + tx * 8 + jj * 4;
            float4 o = make_float4(acc[i][jj*4+0] + bv[jj*4+0], acc[i][jj*4+1] + bv[jj*4+1],
                                   acc[i][jj*4+2] + bv[jj*4+2], acc[i][jj*4+3] + bv[jj*4+3]);
            float* dst;
            if (scatterC) {
                dst = C + (((size_t)((m >> 11) * NH + (n >> 6)) * LSEQ + (m & 2047)) * HDIM)
                        + (n & 63);
            } else {
                dst = C + (size_t)m * DMODEL + n;
            }
            *(float4*)dst = o;
        }
    }
}

// ===========================================================================
// Flash-attention v2 (fp32): in-register softmax via 16-lane shfl reductions.
// Q pre-scaled by 1/sqrt(HD). Only P round-trips smem (once).
// Thread map: ro=(tid>>4)*4 rows, co=(tid&15)*4 cols; a 16-lane half-warp
// shares the same 4 rows -> row reductions are shfl_xor {1,2,4,8}.
// ===========================================================================
__global__ __launch_bounds__(256) void flash2()
{
    extern __shared__ float sm[];
    float* Qs = sm;               // [r][d] stride 68 (pre-scaled)
    float* Kt = sm + SQS;         // [d][t] stride 68
    float* Vs = sm + 2 * SQS;     // [t][d] stride 68
    float* Ps = sm + 3 * SQS;     // [r][t] stride 68

    const int tid = threadIdx.x;
    const int bh  = blockIdx.y;
    const int r0  = blockIdx.x * 64;
    const float NEG_INF = __int_as_float(0xff800000u);

    const float* Qg = g_q + (size_t)bh * (LSEQ * HDIM);
    const float* Kg = g_k + (size_t)bh * (LSEQ * HDIM);
    const float* Vg = g_v + (size_t)bh * (LSEQ * HDIM);

#pragma unroll
    for (int i = 0; i < 4; i++) {
        int idx = tid + i * 256;
        int r = idx >> 4;
        int d4 = (idx & 15) << 2;
        float4 q = *(const float4*)(Qg + (size_t)(r0 + r) * HDIM + d4);
        *(float4*)&Qs[r * 68 + d4] =
            make_float4(q.x * 0.125f, q.y * 0.125f, q.z * 0.125f, q.w * 0.125f);
    }

    const int ro = (tid >> 4) * 4;
    const int co = (tid & 15) * 4;

    float mreg[4], sreg[4];
    float acc[4][4];
#pragma unroll
    for (int i = 0; i < 4; i++) {
        mreg[i] = NEG_INF; sreg[i] = 0.f;
#pragma unroll
        for (int j = 0; j < 4; j++) acc[i][j] = 0.f;
    }

    for (int t0 = 0; t0 < LSEQ; t0 += 64) {
        __syncthreads();   // prior PV reads of Kt/Vs (and Q init) done
#pragma unroll
        for (int i = 0; i < 4; i++) {
            int idx = tid + i * 256;
            int t = idx >> 4;
            int d4 = (idx & 15) << 2;
            float4 kv = *(const float4*)(Kg + (size_t)(t0 + t) * HDIM + d4);
            Kt[(d4 + 0) * 68 + t] = kv.x;
            Kt[(d4 + 1) * 68 + t] = kv.y;
            Kt[(d4 + 2) * 68 + t] = kv.z;
            Kt[(d4 + 3) * 68 + t] = kv.w;
            *(float4*)&Vs[t * 68 + d4] = *(const float4*)(Vg + (size_t)(t0 + t) * HDIM + d4);
        }
        __syncthreads();

        // ---- S = (Q*scale) K^T, register-blocked x4 in d ----
        float sacc[4][4];
#pragma unroll
        for (int i = 0; i < 4; i++)
#pragma unroll
            for (int j = 0; j < 4; j++) sacc[i][j] = 0.f;
#pragma unroll
        for (int d = 0; d < 64; d += 4) {
            float4 q4[4], kv[4];
#pragma unroll
            for (int i = 0; i < 4; i++) q4[i] = *(const float4*)&Qs[(ro + i) * 68 + d];
#pragma unroll
            for (int jj = 0; jj < 4; jj++) kv[jj] = *(const float4*)&Kt[(d + jj) * 68 + co];
#pragma unroll
            for (int i = 0; i < 4; i++) {
                float qa[4] = {q4[i].x, q4[i].y, q4[i].z, q4[i].w};
#pragma unroll
                for (int jj = 0; jj < 4; jj++) {
                    sacc[i][0] += qa[jj] * kv[jj].x;
                    sacc[i][1] += qa[jj] * kv[jj].y;
                    sacc[i][2] += qa[jj] * kv[jj].z;
                    sacc[i][3] += qa[jj] * kv[jj].w;
                }
            }
        }

        // ---- in-register online softmax ----
        float rmax[4], cc[4], rsum[4];
#pragma unroll
        for (int i = 0; i < 4; i++) {
            rmax[i] = fmaxf(fmaxf(sacc[i][0], sacc[i][1]), fmaxf(sacc[i][2], sacc[i][3]));
        }
#pragma unroll
        for (int msk = 1; msk <= 8; msk <<= 1) {
#pragma unroll
            for (int i = 0; i < 4; i++)
                rmax[i] = fmaxf(rmax[i], __shfl_xor_sync(0xffffffffu, rmax[i], msk));
        }
#pragma unroll
        for (int i = 0; i < 4; i++) {
            float mn = fmaxf(mreg[i], rmax[i]);
            cc[i] = __expf(mreg[i] - mn);
            mreg[i] = mn;
            rsum[i] = 0.f;
#pragma unroll
            for (int j = 0; j < 4; j++) {
                float p = __expf(sacc[i][j] - mn);
                sacc[i][j] = p;
                rsum[i] += p;
            }
        }
#pragma unroll
        for (int msk = 1; msk <= 8; msk <<= 1) {
#pragma unroll
            for (int i = 0; i < 4; i++)
                rsum[i] += __shfl_xor_sync(0xffffffffu, rsum[i], msk);
        }
#pragma unroll
        for (int i = 0; i < 4; i++) {
            sreg[i] = sreg[i] * cc[i] + rsum[i];
            *(float4*)&Ps[(ro + i) * 68 + co] =
                make_float4(sacc[i][0], sacc[i][1], sacc[i][2], sacc[i][3]);
#pragma unroll
            for (int j = 0; j < 4; j++) acc[i][j] *= cc[i];
        }
        __syncwarp();   // P rows are produced/consumed within the same half-warp

        // ---- PV, register-blocked x4 in t ----
#pragma unroll
        for (int t = 0; t < 64; t += 4) {
            float4 p4[4], v[4];
#pragma unroll
            for (int i = 0; i < 4; i++) p4[i] = *(const float4*)&Ps[(ro + i) * 68 + t];
#pragma unroll
            for (int jj = 0; jj < 4; jj++) v[jj] = *(const float4*)&Vs[(t + jj) * 68 + co];
#pragma unroll
            for (int i = 0; i < 4; i++) {
                float pa[4] = {p4[i].x, p4[i].y, p4[i].z, p4[i].w};
#pragma unroll
                for (int jj = 0; jj < 4; jj++) {
                    acc[i][0] += pa[jj] * v[jj].x;
                    acc[i][1] += pa[jj] * v[jj].y;
                    acc[i][2] += pa[jj] * v[jj].z;
                    acc[i][3] += pa[jj] * v[jj].w;
                }
            }
        }
    }

    float* Og = g_o + (size_t)bh * (LSEQ * HDIM);
#pragma unroll
    for (int i = 0; i < 4; i++) {
        float inv = 1.0f / sreg[i];
        *(float4*)(Og + (size_t)(r0 + ro + i) * HDIM + co) =
            make_float4(acc[i][0] * inv, acc[i][1] * inv, acc[i][2] * inv, acc[i][3] * inv);
    }
    if ((tid & 15) == 0) {
#pragma unroll
        for (int i = 0; i < 4; i++) {
            g_m[(size_t)bh * LSEQ + r0 + ro + i] = mreg[i];
            g_s[(size_t)bh * LSEQ + r0 + ro + i] = sreg[i];
        }
    }
}

// ---------------------------------------------------------------------------
// Attention-matrix writer (only when out_size includes attention):
// recompute S tilewise, apply stored (m, s), write [B,H,L,T] fp32.
// ---------------------------------------------------------------------------
__global__ __launch_bounds__(256) void attnout_kernel(float* __restrict__ att)
{
    __shared__ float Qs[SQS];
    __shared__ float Kt[SQS];
    __shared__ float mrow[64];
    __shared__ float sinv[64];

    const int tid = threadIdx.x;
    const int bh  = blockIdx.y;
    const int r0  = blockIdx.x * 64;

    const float* Qg = g_q + (size_t)bh * (LSEQ * HDIM);
    const float* Kg = g_k + (size_t)bh * (LSEQ * HDIM);

#pragma unroll
    for (int i = 0; i < 4; i++) {
        int idx = tid + i * 256;
        int r = idx >> 4;
        int d4 = (idx & 15) << 2;
        float4 q = *(const float4*)(Qg + (size_t)(r0 + r) * HDIM + d4);
        *(float4*)&Qs[r * 68 + d4] =
            make_float4(q.x * 0.125f, q.y * 0.125f, q.z * 0.125f, q.w * 0.125f);
    }
    if (tid < 64) {
        mrow[tid] = g_m[(size_t)bh * LSEQ + r0 + tid];
        sinv[tid] = 1.0f / g_s[(size_t)bh * LSEQ + r0 + tid];
    }

    const int ro = (tid >> 4) * 4;
    const int co = (tid & 15) * 4;

    for (int t0 = 0; t0 < LSEQ; t0 += 64) {
        __syncthreads();
#pragma unroll
        for (int i = 0; i < 4; i++) {
            int idx = tid + i * 256;
            int t = idx >> 4;
            int d4 = (idx & 15) << 2;
            float4 kv = *(const float4*)(Kg + (size_t)(t0 + t) * HDIM + d4);
            Kt[(d4 + 0) * 68 + t] = kv.x;
            Kt[(d4 + 1) * 68 + t] = kv.y;
            Kt[(d4 + 2) * 68 + t] = kv.z;
            Kt[(d4 + 3) * 68 + t] = kv.w;
        }
        __syncthreads();

        float sacc[4][4];
#pragma unroll
        for (int i = 0; i < 4; i++)
#pragma unroll
            for (int j = 0; j < 4; j++) sacc[i][j] = 0.f;
#pragma unroll
        for (int d = 0; d < 64; d += 4) {
            float4 q4[4], kv[4];
#pragma unroll
            for (int i = 0; i < 4; i++) q4[i] = *(const float4*)&Qs[(ro + i) * 68 + d];
#pragma unroll
            for (int jj = 0; jj < 4; jj++) kv[jj] = *(const float4*)&Kt[(d + jj) * 68 + co];
#pragma unroll
            for (int i = 0; i < 4; i++) {
                float qa[4] = {q4[i].x, q4[i].y, q4[i].z, q4[i].w};
#pragma unroll
                for (int jj = 0; jj < 4; jj++) {
                    sacc[i][0] += qa[jj] * kv[jj].x;
                    sacc[i][1] += qa[jj] * kv[jj].y;
                    sacc[i][2] += qa[jj] * kv[jj].z;
                    sacc[i][3] += qa[jj] * kv[jj].w;
                }
            }
        }
#pragma unroll
        for (int i = 0; i < 4; i++) {
            float mi = mrow[ro + i];
            float si = sinv[ro + i];
            float4 o = make_float4(__expf(sacc[i][0] - mi) * si,
                                   __expf(sacc[i][1] - mi) * si,
                                   __expf(sacc[i][2] - mi) * si,
                                   __expf(sacc[i][3] - mi) * si);
            *(float4*)(att + ((size_t)bh * LSEQ + r0 + ro + i) * LSEQ + t0 + co) = o;
        }
    }
}

// ---------------------------------------------------------------------------
extern "C" void kernel_launch(void* const* d_in, const int* in_sizes, int n_in,
                              void* d_out, int out_size)
{
    const float* query = (const float*)d_in[0];
    const float* key   = (const float*)d_in[1];
    const float* value = (const float*)d_in[2];
    const float* Wq    = (const float*)d_in[3];
    const float* Wk    = (const float*)d_in[4];
    const float* Wv    = (const float*)d_in[5];
    const float* Wo    = (const float*)d_in[6];
    const float* bo    = (const float*)d_in[7];
    float* out = (float*)d_out;

    float *qp, *kp, *vp, *op;
    cudaGetSymbolAddress((void**)&qp, g_q);
    cudaGetSymbolAddress((void**)&kp, g_k);
    cudaGetSymbolAddress((void**)&vp, g_v);
    cudaGetSymbolAddress((void**)&op, g_o);

    cudaFuncSetAttribute(gemm2, cudaFuncAttributeMaxDynamicSharedMemorySize, G_SMEM_B);
    dim3 gg(DMODEL / 128, M_TOT / 128);  // (8, 64)
    gemm2<<<gg, 256, G_SMEM_B>>>(query, Wq, nullptr, qp, 0, 1);
    gemm2<<<gg, 256, G_SMEM_B>>>(key,   Wk, nullptr, kp, 0, 1);
    gemm2<<<gg, 256, G_SMEM_B>>>(value, Wv, nullptr, vp, 0, 1);

    int shm = 4 * SQS * (int)sizeof(float);  // 69632 bytes
    cudaFuncSetAttribute(flash2, cudaFuncAttributeMaxDynamicSharedMemorySize, shm);
    flash2<<<dim3(LSEQ / 64, NB * NH), 256, shm>>>();

    gemm2<<<gg, 256, G_SMEM_B>>>(op, Wo, bo, out, 1, 0);

    if (out_size > OUT_ELEMS) {
        attnout_kernel<<<dim3(LSEQ / 64, NB * NH), 256>>>(out + OUT_ELEMS);
    }
}

// round 10
// speedup vs baseline: 1.0329x; 1.0183x over previous
#include <cuda_runtime.h>
#include <cstdint>

#define NB 4
#define NH 16
#define LSEQ 2048
#define HDIM 64
#define DMODEL 1024
#define M_TOT (NB*LSEQ)            // 8192
#define OUT_ELEMS (M_TOT*DMODEL)   // 8388608
#define SQS (64*68)

// GEMM tiling: BM=128, BN=128, BK=32, 256 threads, 8x8/thread, double-buffered
#define GBK 32
#define GNCHUNK (DMODEL/GBK)       // 32
#define G_TILE_F (GBK*132)         // floats per (A or B) buffer: 4224
#define G_SMEM_B (4*G_TILE_F*4)    // 2 bufs x (A+B) = 67584 bytes

typedef unsigned long long u64;

// ---- packed fp32x2 helpers (Blackwell base-ISA; 1 instr = 2 IEEE fp32 FMAs) ----
__device__ __forceinline__ u64 pk2(float lo, float hi) {
    u64 r; asm("mov.b64 %0, {%1, %2};" : "=l"(r) : "f"(lo), "f"(hi)); return r;
}
__device__ __forceinline__ void upk2(u64 v, float& lo, float& hi) {
    asm("mov.b64 {%0, %1}, %2;" : "=f"(lo), "=f"(hi) : "l"(v));
}
__device__ __forceinline__ void fma2(u64& d, u64 a, u64 b) {
    asm("fma.rn.f32x2 %0, %1, %2, %3;" : "=l"(d) : "l"(a), "l"(b), "l"(d));
}
__device__ __forceinline__ void mul2(u64& d, u64 a, u64 b) {
    asm("mul.rn.f32x2 %0, %1, %2;" : "=l"(d) : "l"(a), "l"(b));
}

// Scratch (device globals; no allocation allowed)
__device__ float g_q[NB*NH*LSEQ*HDIM];
__device__ float g_k[NB*NH*LSEQ*HDIM];
__device__ float g_v[NB*NH*LSEQ*HDIM];
__device__ float g_o[NB*NH*LSEQ*HDIM];
__device__ float g_m[NB*NH*LSEQ];
__device__ float g_s[NB*NH*LSEQ];

// rank-1 update: s[i][0..1] += a_i * (kv.x,kv.y | kv.z,kv.w), 4 rows packed
__device__ __forceinline__ void rank1p(u64 s[4][2], float a0, float a1, float a2,
                                       float a3, float4 kvv) {
    u64 kA = pk2(kvv.x, kvv.y), kB = pk2(kvv.z, kvv.w);
    u64 p;
    p = pk2(a0, a0); fma2(s[0][0], p, kA); fma2(s[0][1], p, kB);
    p = pk2(a1, a1); fma2(s[1][0], p, kA); fma2(s[1][1], p, kB);
    p = pk2(a2, a2); fma2(s[2][0], p, kA); fma2(s[2][1], p, kB);
    p = pk2(a3, a3); fma2(s[3][0], p, kA); fma2(s[3][1], p, kB);
}

// ===========================================================================
// SIMT GEMM v3 (packed f32x2): C[m,n] = sum_k A[m,k] * W[n,k] (+ bias[n])
// 128x128 tile, BK=32, 256 threads, 8 rows x 4 col-pairs per thread.
// gatherA: A read from head-split [B,H,L,HD]; scatterC: C written head-split.
// ===========================================================================
__global__ __launch_bounds__(256) void gemm3(
    const float* __restrict__ A, const float* __restrict__ W,
    const float* __restrict__ bias, float* __restrict__ C,
    int gatherA, int scatterC)
{
    extern __shared__ float gsm[];
    const int tid = threadIdx.x;
    const int tx = tid & 15;         // n groups of 8
    const int ty = tid >> 4;         // m groups of 8
    const int m0 = blockIdx.y * 128;
    const int n0 = blockIdx.x * 128;

    const int lr  = tid >> 3;            // load row base; +32 per i
    const int lc4 = (tid & 7) << 2;      // load k offset

    u64 acc2[8][4];
#pragma unroll
    for (int i = 0; i < 8; i++)
#pragma unroll
        for (int j = 0; j < 4; j++) acc2[i][j] = 0ull;

    float4 ra[4], rb[4];
#pragma unroll
    for (int i = 0; i < 4; i++) {
        int r = lr + i * 32;
        if (!gatherA) {
            ra[i] = *(const float4*)(A + (size_t)(m0 + r) * DMODEL + lc4);
        } else {
            int m = m0 + r, k = lc4;
            ra[i] = *(const float4*)(A +
                (((size_t)((m >> 11) * NH + (k >> 6)) * LSEQ + (m & 2047)) * HDIM) + (k & 63));
        }
        rb[i] = *(const float4*)(W + (size_t)(n0 + r) * DMODEL + lc4);
    }

    for (int c = 0; c < GNCHUNK; c++) {
        const int buf = c & 1;
        float* As = gsm + buf * G_TILE_F;
        float* Bs = gsm + 2 * G_TILE_F + buf * G_TILE_F;

#pragma unroll
        for (int i = 0; i < 4; i++) {
            int r = lr + i * 32;
            As[(lc4 + 0) * 132 + r] = ra[i].x;
            As[(lc4 + 1) * 132 + r] = ra[i].y;
            As[(lc4 + 2) * 132 + r] = ra[i].z;
            As[(lc4 + 3) * 132 + r] = ra[i].w;
            Bs[(lc4 + 0) * 132 + r] = rb[i].x;
            Bs[(lc4 + 1) * 132 + r] = rb[i].y;
            Bs[(lc4 + 2) * 132 + r] = rb[i].z;
            Bs[(lc4 + 3) * 132 + r] = rb[i].w;
        }
        __syncthreads();

        if (c + 1 < GNCHUNK) {
            int k0 = (c + 1) * GBK;
#pragma unroll
            for (int i = 0; i < 4; i++) {
                int r = lr + i * 32;
                if (!gatherA) {
                    ra[i] = *(const float4*)(A + (size_t)(m0 + r) * DMODEL + k0 + lc4);
                } else {
                    int m = m0 + r, k = k0 + lc4;
                    ra[i] = *(const float4*)(A +
                        (((size_t)((m >> 11) * NH + (k >> 6)) * LSEQ + (m & 2047)) * HDIM) + (k & 63));
                }
                rb[i] = *(const float4*)(W + (size_t)(n0 + r) * DMODEL + k0 + lc4);
            }
        }

#pragma unroll
        for (int k = 0; k < GBK; k++) {
            float4 a0 = *(const float4*)&As[k * 132 + ty * 8];
            float4 a1 = *(const float4*)&As[k * 132 + ty * 8 + 4];
            float4 b0 = *(const float4*)&Bs[k * 132 + tx * 8];
            float4 b1 = *(const float4*)&Bs[k * 132 + tx * 8 + 4];
            u64 bp[4] = {pk2(b0.x, b0.y), pk2(b0.z, b0.w),
                         pk2(b1.x, b1.y), pk2(b1.z, b1.w)};
            float av[8] = {a0.x, a0.y, a0.z, a0.w, a1.x, a1.y, a1.z, a1.w};
#pragma unroll
            for (int i = 0; i < 8; i++) {
                u64 ap = pk2(av[i], av[i]);
#pragma unroll
                for (int j = 0; j < 4; j++) fma2(acc2[i][j], ap, bp[j]);
            }
        }
        __syncthreads();
    }

    // ---- epilogue ----
    float bv[8] = {0, 0, 0, 0, 0, 0, 0, 0};
    if (bias) {
        float4 b0 = *(const float4*)(bias + n0 + tx * 8);
        float4 b1 = *(const float4*)(bias + n0 + tx * 8 + 4);
        bv[0] = b0.x; bv[1] = b0.y; bv[2] = b0.z; bv[3] = b0.w;
        bv[4] = b1.x; bv[5] = b1.y; bv[6] = b1.z; bv[7] = b1.w;
    }
#pragma unroll
    for (int i = 0; i < 8; i++) {
        int m = m0 + ty * 8 + i;
        float cf[8];
        upk2(acc2[i][0], cf[0], cf[1]);
        upk2(acc2[i][1], cf[2], cf[3]);
        upk2(acc2[i][2], cf[4], cf[5]);
        upk2(acc2[i][3], cf[6], cf[7]);
#pragma unroll
        for (int jj = 0; jj < 2; jj++) {
            int n = n0 + tx * 8 + jj * 4;
            float4 o = make_float4(cf[jj*4+0] + bv[jj*4+0], cf[jj*4+1] + bv[jj*4+1],
                                   cf[jj*4+2] + bv[jj*4+2], cf[jj*4+3] + bv[jj*4+3]);
            float* dst;
            if (scatterC) {
                dst = C + (((size_t)((m >> 11) * NH + (n >> 6)) * LSEQ + (m & 2047)) * HDIM)
                        + (n & 63);
            } else {
                dst = C + (size_t)m * DMODEL + n;
            }
            *(float4*)dst = o;
        }
    }
}

// ===========================================================================
// Flash-attention v3 (packed f32x2): structure identical to R5 flash2 (passed);
// S and PV inner products use fma.rn.f32x2 on column pairs.
// ===========================================================================
__global__ __launch_bounds__(256) void flash3()
{
    extern __shared__ float sm[];
    float* Qs = sm;               // [r][d] stride 68 (pre-scaled)
    float* Kt = sm + SQS;         // [d][t] stride 68
    float* Vs = sm + 2 * SQS;     // [t][d] stride 68
    float* Ps = sm + 3 * SQS;     // [r][t] stride 68

    const int tid = threadIdx.x;
    const int bh  = blockIdx.y;
    const int r0  = blockIdx.x * 64;
    const float NEG_INF = __int_as_float(0xff800000u);

    const float* Qg = g_q + (size_t)bh * (LSEQ * HDIM);
    const float* Kg = g_k + (size_t)bh * (LSEQ * HDIM);
    const float* Vg = g_v + (size_t)bh * (LSEQ * HDIM);

#pragma unroll
    for (int i = 0; i < 4; i++) {
        int idx = tid + i * 256;
        int r = idx >> 4;
        int d4 = (idx & 15) << 2;
        float4 q = *(const float4*)(Qg + (size_t)(r0 + r) * HDIM + d4);
        *(float4*)&Qs[r * 68 + d4] =
            make_float4(q.x * 0.125f, q.y * 0.125f, q.z * 0.125f, q.w * 0.125f);
    }

    const int ro = (tid >> 4) * 4;
    const int co = (tid & 15) * 4;

    float mreg[4], sreg[4];
    u64 acc2[4][2];
#pragma unroll
    for (int i = 0; i < 4; i++) {
        mreg[i] = NEG_INF; sreg[i] = 0.f;
        acc2[i][0] = 0ull; acc2[i][1] = 0ull;
    }

    for (int t0 = 0; t0 < LSEQ; t0 += 64) {
        __syncthreads();
#pragma unroll
        for (int i = 0; i < 4; i++) {
            int idx = tid + i * 256;
            int t = idx >> 4;
            int d4 = (idx & 15) << 2;
            float4 kv = *(const float4*)(Kg + (size_t)(t0 + t) * HDIM + d4);
            Kt[(d4 + 0) * 68 + t] = kv.x;
            Kt[(d4 + 1) * 68 + t] = kv.y;
            Kt[(d4 + 2) * 68 + t] = kv.z;
            Kt[(d4 + 3) * 68 + t] = kv.w;
            *(float4*)&Vs[t * 68 + d4] = *(const float4*)(Vg + (size_t)(t0 + t) * HDIM + d4);
        }
        __syncthreads();

        // ---- S = (Q*scale) K^T, packed col pairs ----
        u64 sacc2[4][2] = {{0ull, 0ull}, {0ull, 0ull}, {0ull, 0ull}, {0ull, 0ull}};
#pragma unroll
        for (int d = 0; d < 64; d += 4) {
            float4 q4[4], kv[4];
#pragma unroll
            for (int i = 0; i < 4; i++) q4[i] = *(const float4*)&Qs[(ro + i) * 68 + d];
#pragma unroll
            for (int jj = 0; jj < 4; jj++) kv[jj] = *(const float4*)&Kt[(d + jj) * 68 + co];
            rank1p(sacc2, q4[0].x, q4[1].x, q4[2].x, q4[3].x, kv[0]);
            rank1p(sacc2, q4[0].y, q4[1].y, q4[2].y, q4[3].y, kv[1]);
            rank1p(sacc2, q4[0].z, q4[1].z, q4[2].z, q4[3].z, kv[2]);
            rank1p(sacc2, q4[0].w, q4[1].w, q4[2].w, q4[3].w, kv[3]);
        }

        // ---- unpack, in-register online softmax (same as R5) ----
        float sacc[4][4];
#pragma unroll
        for (int i = 0; i < 4; i++) {
            upk2(sacc2[i][0], sacc[i][0], sacc[i][1]);
            upk2(sacc2[i][1], sacc[i][2], sacc[i][3]);
        }
        float rmax[4], cc[4], rsum[4];
#pragma unroll
        for (int i = 0; i < 4; i++)
            rmax[i] = fmaxf(fmaxf(sacc[i][0], sacc[i][1]), fmaxf(sacc[i][2], sacc[i][3]));
#pragma unroll
        for (int msk = 1; msk <= 8; msk <<= 1) {
#pragma unroll
            for (int i = 0; i < 4; i++)
                rmax[i] = fmaxf(rmax[i], __shfl_xor_sync(0xffffffffu, rmax[i], msk));
        }
#pragma unroll
        for (int i = 0; i < 4; i++) {
            float mn = fmaxf(mreg[i], rmax[i]);
            cc[i] = __expf(mreg[i] - mn);
            mreg[i] = mn;
            rsum[i] = 0.f;
#pragma unroll
            for (int j = 0; j < 4; j++) {
                float p = __expf(sacc[i][j] - mn);
                sacc[i][j] = p;
                rsum[i] += p;
            }
        }
#pragma unroll
        for (int msk = 1; msk <= 8; msk <<= 1) {
#pragma unroll
            for (int i = 0; i < 4; i++)
                rsum[i] += __shfl_xor_sync(0xffffffffu, rsum[i], msk);
        }
#pragma unroll
        for (int i = 0; i < 4; i++) {
            sreg[i] = sreg[i] * cc[i] + rsum[i];
            *(float4*)&Ps[(ro + i) * 68 + co] =
                make_float4(sacc[i][0], sacc[i][1], sacc[i][2], sacc[i][3]);
            u64 cp = pk2(cc[i], cc[i]);
            mul2(acc2[i][0], acc2[i][0], cp);
            mul2(acc2[i][1], acc2[i][1], cp);
        }
        __syncwarp();   // P rows produced/consumed within the same half-warp

        // ---- PV, packed col pairs ----
#pragma unroll
        for (int t = 0; t < 64; t += 4) {
            float4 p4[4], v[4];
#pragma unroll
            for (int i = 0; i < 4; i++) p4[i] = *(const float4*)&Ps[(ro + i) * 68 + t];
#pragma unroll
            for (int jj = 0; jj < 4; jj++) v[jj] = *(const float4*)&Vs[(t + jj) * 68 + co];
            rank1p(acc2, p4[0].x, p4[1].x, p4[2].x, p4[3].x, v[0]);
            rank1p(acc2, p4[0].y, p4[1].y, p4[2].y, p4[3].y, v[1]);
            rank1p(acc2, p4[0].z, p4[1].z, p4[2].z, p4[3].z, v[2]);
            rank1p(acc2, p4[0].w, p4[1].w, p4[2].w, p4[3].w, v[3]);
        }
    }

    float* Og = g_o + (size_t)bh * (LSEQ * HDIM);
#pragma unroll
    for (int i = 0; i < 4; i++) {
        float inv = 1.0f / sreg[i];
        float o0, o1, o2, o3;
        upk2(acc2[i][0], o0, o1);
        upk2(acc2[i][1], o2, o3);
        *(float4*)(Og + (size_t)(r0 + ro + i) * HDIM + co) =
            make_float4(o0 * inv, o1 * inv, o2 * inv, o3 * inv);
    }
    if ((tid & 15) == 0) {
#pragma unroll
        for (int i = 0; i < 4; i++) {
            g_m[(size_t)bh * LSEQ + r0 + ro + i] = mreg[i];
            g_s[(size_t)bh * LSEQ + r0 + ro + i] = sreg[i];
        }
    }
}

// ---------------------------------------------------------------------------
// Attention-matrix writer (only when out_size includes attention):
// recompute S tilewise, apply stored (m, s), write [B,H,L,T] fp32.
// ---------------------------------------------------------------------------
__global__ __launch_bounds__(256) void attnout_kernel(float* __restrict__ att)
{
    __shared__ float Qs[SQS];
    __shared__ float Kt[SQS];
    __shared__ float mrow[64];
    __shared__ float sinv[64];

    const int tid = threadIdx.x;
    const int bh  = blockIdx.y;
    const int r0  = blockIdx.x * 64;

    const float* Qg = g_q + (size_t)bh * (LSEQ * HDIM);
    const float* Kg = g_k + (size_t)bh * (LSEQ * HDIM);

#pragma unroll
    for (int i = 0; i < 4; i++) {
        int idx = tid + i * 256;
        int r = idx >> 4;
        int d4 = (idx & 15) << 2;
        float4 q = *(const float4*)(Qg + (size_t)(r0 + r) * HDIM + d4);
        *(float4*)&Qs[r * 68 + d4] =
            make_float4(q.x * 0.125f, q.y * 0.125f, q.z * 0.125f, q.w * 0.125f);
    }
    if (tid < 64) {
        mrow[tid] = g_m[(size_t)bh * LSEQ + r0 + tid];
        sinv[tid] = 1.0f / g_s[(size_t)bh * LSEQ + r0 + tid];
    }

    const int ro = (tid >> 4) * 4;
    const int co = (tid & 15) * 4;

    for (int t0 = 0; t0 < LSEQ; t0 += 64) {
        __syncthreads();
#pragma unroll
        for (int i = 0; i < 4; i++) {
            int idx = tid + i * 256;
            int t = idx >> 4;
            int d4 = (idx & 15) << 2;
            float4 kv = *(const float4*)(Kg + (size_t)(t0 + t) * HDIM + d4);
            Kt[(d4 + 0) * 68 + t] = kv.x;
            Kt[(d4 + 1) * 68 + t] = kv.y;
            Kt[(d4 + 2) * 68 + t] = kv.z;
            Kt[(d4 + 3) * 68 + t] = kv.w;
        }
        __syncthreads();

        u64 sacc2[4][2] = {{0ull, 0ull}, {0ull, 0ull}, {0ull, 0ull}, {0ull, 0ull}};
#pragma unroll
        for (int d = 0; d < 64; d += 4) {
            float4 q4[4], kv[4];
#pragma unroll
            for (int i = 0; i < 4; i++) q4[i] = *(const float4*)&Qs[(ro + i) * 68 + d];
#pragma unroll
            for (int jj = 0; jj < 4; jj++) kv[jj] = *(const float4*)&Kt[(d + jj) * 68 + co];
            rank1p(sacc2, q4[0].x, q4[1].x, q4[2].x, q4[3].x, kv[0]);
            rank1p(sacc2, q4[0].y, q4[1].y, q4[2].y, q4[3].y, kv[1]);
            rank1p(sacc2, q4[0].z, q4[1].z, q4[2].z, q4[3].z, kv[2]);
            rank1p(sacc2, q4[0].w, q4[1].w, q4[2].w, q4[3].w, kv[3]);
        }
#pragma unroll
        for (int i = 0; i < 4; i++) {
            float s0, s1, s2, s3;
            upk2(sacc2[i][0], s0, s1);
            upk2(sacc2[i][1], s2, s3);
            float mi = mrow[ro + i];
            float si = sinv[ro + i];
            float4 o = make_float4(__expf(s0 - mi) * si, __expf(s1 - mi) * si,
                                   __expf(s2 - mi) * si, __expf(s3 - mi) * si);
            *(float4*)(att + ((size_t)bh * LSEQ + r0 + ro + i) * LSEQ + t0 + co) = o;
        }
    }
}

// ---------------------------------------------------------------------------
extern "C" void kernel_launch(void* const* d_in, const int* in_sizes, int n_in,
                              void* d_out, int out_size)
{
    const float* query = (const float*)d_in[0];
    const float* key   = (const float*)d_in[1];
    const float* value = (const float*)d_in[2];
    const float* Wq    = (const float*)d_in[3];
    const float* Wk    = (const float*)d_in[4];
    const float* Wv    = (const float*)d_in[5];
    const float* Wo    = (const float*)d_in[6];
    const float* bo    = (const float*)d_in[7];
    float* out = (float*)d_out;

    float *qp, *kp, *vp, *op;
    cudaGetSymbolAddress((void**)&qp, g_q);
    cudaGetSymbolAddress((void**)&kp, g_k);
    cudaGetSymbolAddress((void**)&vp, g_v);
    cudaGetSymbolAddress((void**)&op, g_o);

    cudaFuncSetAttribute(gemm3, cudaFuncAttributeMaxDynamicSharedMemorySize, G_SMEM_B);
    dim3 gg(DMODEL / 128, M_TOT / 128);  // (8, 64)
    gemm3<<<gg, 256, G_SMEM_B>>>(query, Wq, nullptr, qp, 0, 1);
    gemm3<<<gg, 256, G_SMEM_B>>>(key,   Wk, nullptr, kp, 0, 1);
    gemm3<<<gg, 256, G_SMEM_B>>>(value, Wv, nullptr, vp, 0, 1);

    int shm = 4 * SQS * (int)sizeof(float);  // 69632
    cudaFuncSetAttribute(flash3, cudaFuncAttributeMaxDynamicSharedMemorySize, shm);
    flash3<<<dim3(LSEQ / 64, NB * NH), 256, shm>>>();

    gemm3<<<gg, 256, G_SMEM_B>>>(op, Wo, bo, out, 1, 0);

    if (out_size > OUT_ELEMS) {
        attnout_kernel<<<dim3(LSEQ / 64, NB * NH), 256>>>(out + OUT_ELEMS);
    }
}

// round 12
// speedup vs baseline: 1.1804x; 1.1428x over previous
#include <cuda_runtime.h>
#include <cstdint>

#define NB 4
#define NH 16
#define LSEQ 2048
#define HDIM 64
#define DMODEL 1024
#define M_TOT (NB*LSEQ)            // 8192
#define OUT_ELEMS (M_TOT*DMODEL)   // 8388608
#define SQS (64*68)

// GEMM v4 tiling: BM=128, BN=128, BK=32, 128 threads, 8x16/thread, double-buffered
#define GBK 32
#define GNCHUNK (DMODEL/GBK)       // 32
#define G_TILE_F (GBK*132)         // floats per (A or B) buffer: 4224
#define G_SMEM_B (4*G_TILE_F*4)    // 2 bufs x (A+B) = 67584 bytes

// flash4: Q-block 128 rows, 128 threads, 8x8/thread
#define FSHM ((128+64+64+128)*68*4)   // Qs,Kt,Vs,Ps = 104448 bytes

typedef unsigned long long u64;

// ---- packed fp32x2 helpers ----
__device__ __forceinline__ u64 pk2(float lo, float hi) {
    u64 r; asm("mov.b64 %0, {%1, %2};" : "=l"(r) : "f"(lo), "f"(hi)); return r;
}
__device__ __forceinline__ void upk2(u64 v, float& lo, float& hi) {
    asm("mov.b64 {%0, %1}, %2;" : "=f"(lo), "=f"(hi) : "l"(v));
}
__device__ __forceinline__ void fma2(u64& d, u64 a, u64 b) {
    asm("fma.rn.f32x2 %0, %1, %2, %3;" : "=l"(d) : "l"(a), "l"(b), "l"(d));
}
__device__ __forceinline__ void mul2(u64& d, u64 a, u64 b) {
    asm("mul.rn.f32x2 %0, %1, %2;" : "=l"(d) : "l"(a), "l"(b));
}

// Scratch (device globals; no allocation allowed)
__device__ float g_q[NB*NH*LSEQ*HDIM];
__device__ float g_k[NB*NH*LSEQ*HDIM];
__device__ float g_v[NB*NH*LSEQ*HDIM];
__device__ float g_o[NB*NH*LSEQ*HDIM];
__device__ float g_m[NB*NH*LSEQ];
__device__ float g_s[NB*NH*LSEQ];

// ===========================================================================
// GEMM v4 (packed f32x2, 0.75 B/MAC): C[m,n] = sum_k A[m,k]*W[n,k] (+bias[n])
// 128x128 tile, BK=32, 128 threads; per thread 8 rows x 16 cols
// (col quads at tx*4 + {0,32,64,96} -> conflict-free octet LDS).
// gatherA: A read from head-split [B,H,L,HD]; scatterC: C written head-split.
// ===========================================================================
__global__ __launch_bounds__(128) void gemm4(
    const float* __restrict__ A, const float* __restrict__ W,
    const float* __restrict__ bias, float* __restrict__ C,
    int gatherA, int scatterC)
{
    extern __shared__ float gsm[];
    const int tid = threadIdx.x;
    const int tx = tid & 7;          // col group: cols tx*4 + g*32
    const int ty = tid >> 3;         // row group: rows ty*8..+7
    const int m0 = blockIdx.y * 128;
    const int n0 = blockIdx.x * 128;

    u64 acc2[8][8];
#pragma unroll
    for (int i = 0; i < 8; i++)
#pragma unroll
        for (int j = 0; j < 8; j++) acc2[i][j] = 0ull;

    // global load coords: 8 float4 per side per chunk
    // idx = tid + ii*128 ; r = idx>>3 (0..127), c4 = (idx&7)*4
    float4 ra[8], rb[8];
#pragma unroll
    for (int ii = 0; ii < 8; ii++) {
        int idx = tid + ii * 128;
        int r = idx >> 3;
        int c4 = (idx & 7) << 2;
        if (!gatherA) {
            ra[ii] = *(const float4*)(A + (size_t)(m0 + r) * DMODEL + c4);
        } else {
            int m = m0 + r, k = c4;
            ra[ii] = *(const float4*)(A +
                (((size_t)((m >> 11) * NH + (k >> 6)) * LSEQ + (m & 2047)) * HDIM) + (k & 63));
        }
        rb[ii] = *(const float4*)(W + (size_t)(n0 + r) * DMODEL + c4);
    }

    for (int c = 0; c < GNCHUNK; c++) {
        const int buf = c & 1;
        float* As = gsm + buf * G_TILE_F;
        float* Bs = gsm + 2 * G_TILE_F + buf * G_TILE_F;

        // store chunk c (transposed: [k][row])
#pragma unroll
        for (int ii = 0; ii < 8; ii++) {
            int idx = tid + ii * 128;
            int r = idx >> 3;
            int c4 = (idx & 7) << 2;
            As[(c4 + 0) * 132 + r] = ra[ii].x;
            As[(c4 + 1) * 132 + r] = ra[ii].y;
            As[(c4 + 2) * 132 + r] = ra[ii].z;
            As[(c4 + 3) * 132 + r] = ra[ii].w;
            Bs[(c4 + 0) * 132 + r] = rb[ii].x;
            Bs[(c4 + 1) * 132 + r] = rb[ii].y;
            Bs[(c4 + 2) * 132 + r] = rb[ii].z;
            Bs[(c4 + 3) * 132 + r] = rb[ii].w;
        }
        __syncthreads();

        // prefetch next chunk (hidden under compute)
        if (c + 1 < GNCHUNK) {
            int k0 = (c + 1) * GBK;
#pragma unroll
            for (int ii = 0; ii < 8; ii++) {
                int idx = tid + ii * 128;
                int r = idx >> 3;
                int c4 = (idx & 7) << 2;
                if (!gatherA) {
                    ra[ii] = *(const float4*)(A + (size_t)(m0 + r) * DMODEL + k0 + c4);
                } else {
                    int m = m0 + r, k = k0 + c4;
                    ra[ii] = *(const float4*)(A +
                        (((size_t)((m >> 11) * NH + (k >> 6)) * LSEQ + (m & 2047)) * HDIM) + (k & 63));
                }
                rb[ii] = *(const float4*)(W + (size_t)(n0 + r) * DMODEL + k0 + c4);
            }
        }

        // compute: per k, 2 A loads + 4 B loads -> 128 MACs
#pragma unroll
        for (int k = 0; k < GBK; k++) {
            float4 a0 = *(const float4*)&As[k * 132 + ty * 8];
            float4 a1 = *(const float4*)&As[k * 132 + ty * 8 + 4];
            u64 bp[8];
#pragma unroll
            for (int gq = 0; gq < 4; gq++) {
                float4 b = *(const float4*)&Bs[k * 132 + tx * 4 + gq * 32];
                bp[gq * 2 + 0] = pk2(b.x, b.y);
                bp[gq * 2 + 1] = pk2(b.z, b.w);
            }
            float av[8] = {a0.x, a0.y, a0.z, a0.w, a1.x, a1.y, a1.z, a1.w};
#pragma unroll
            for (int i = 0; i < 8; i++) {
                u64 ap = pk2(av[i], av[i]);
#pragma unroll
                for (int j = 0; j < 8; j++) fma2(acc2[i][j], ap, bp[j]);
            }
        }
        __syncthreads();
    }

    // ---- epilogue ----
#pragma unroll
    for (int i = 0; i < 8; i++) {
        int m = m0 + ty * 8 + i;
#pragma unroll
        for (int gq = 0; gq < 4; gq++) {
            int n = n0 + tx * 4 + gq * 32;
            float f0, f1, f2, f3;
            upk2(acc2[i][gq * 2 + 0], f0, f1);
            upk2(acc2[i][gq * 2 + 1], f2, f3);
            if (bias) {
                float4 bv = *(const float4*)(bias + n);
                f0 += bv.x; f1 += bv.y; f2 += bv.z; f3 += bv.w;
            }
            float4 o = make_float4(f0, f1, f2, f3);
            float* dst;
            if (scatterC) {
                dst = C + (((size_t)((m >> 11) * NH + (n >> 6)) * LSEQ + (m & 2047)) * HDIM)
                        + (n & 63);
            } else {
                dst = C + (size_t)m * DMODEL + n;
            }
            *(float4*)dst = o;
        }
    }
}

// ===========================================================================
// Flash-attention v4 (packed f32x2, 1 B/MAC):
// Q-block 128 rows, 128 threads; per thread 8 rows x 8 cols
// (cols tx*4 and 32+tx*4). Octet-level softmax reductions via shfl.
// ===========================================================================
__global__ __launch_bounds__(128) void flash4()
{
    extern __shared__ float sm[];
    float* Qs = sm;                    // [128][68] pre-scaled
    float* Kt = sm + 128 * 68;         // [d][t] 64x68
    float* Vs = Kt + 64 * 68;          // [t][d] 64x68
    float* Ps = Vs + 64 * 68;          // [128][68]

    const int tid = threadIdx.x;
    const int bh  = blockIdx.y;
    const int r0  = blockIdx.x * 128;
    const int tx = tid & 7;
    const int ty = tid >> 3;
    const int ro = ty * 8;
    const float NEG_INF = __int_as_float(0xff800000u);

    const float* Qg = g_q + (size_t)bh * (LSEQ * HDIM);
    const float* Kg = g_k + (size_t)bh * (LSEQ * HDIM);
    const float* Vg = g_v + (size_t)bh * (LSEQ * HDIM);

    // load Q block (pre-scaled by 1/8)
#pragma unroll
    for (int i = 0; i < 16; i++) {
        int idx = tid + i * 128;
        int r = idx >> 4;
        int d4 = (idx & 15) << 2;
        float4 q = *(const float4*)(Qg + (size_t)(r0 + r) * HDIM + d4);
        *(float4*)&Qs[r * 68 + d4] =
            make_float4(q.x * 0.125f, q.y * 0.125f, q.z * 0.125f, q.w * 0.125f);
    }

    float mreg[8], sreg[8];
    u64 acc2[8][4];
#pragma unroll
    for (int i = 0; i < 8; i++) {
        mreg[i] = NEG_INF; sreg[i] = 0.f;
#pragma unroll
        for (int j = 0; j < 4; j++) acc2[i][j] = 0ull;
    }

    for (int t0 = 0; t0 < LSEQ; t0 += 64) {
        __syncthreads();   // prior-iter Kt/Vs reads done (also covers Q init)
#pragma unroll
        for (int i = 0; i < 8; i++) {
            int idx = tid + i * 128;
            int t = idx >> 4;
            int d4 = (idx & 15) << 2;
            float4 kv = *(const float4*)(Kg + (size_t)(t0 + t) * HDIM + d4);
            Kt[(d4 + 0) * 68 + t] = kv.x;
            Kt[(d4 + 1) * 68 + t] = kv.y;
            Kt[(d4 + 2) * 68 + t] = kv.z;
            Kt[(d4 + 3) * 68 + t] = kv.w;
            *(float4*)&Vs[t * 68 + d4] = *(const float4*)(Vg + (size_t)(t0 + t) * HDIM + d4);
        }
        __syncthreads();

        // ---- S = (Q*scale) K^T : 8 rows x 8 t-cols per thread ----
        u64 sacc2[8][4];
#pragma unroll
        for (int i = 0; i < 8; i++)
#pragma unroll
            for (int j = 0; j < 4; j++) sacc2[i][j] = 0ull;

#pragma unroll
        for (int d = 0; d < 64; d += 4) {
            u64 kp[4][4];
#pragma unroll
            for (int jj = 0; jj < 4; jj++) {
                float4 k0 = *(const float4*)&Kt[(d + jj) * 68 + tx * 4];
                float4 k1 = *(const float4*)&Kt[(d + jj) * 68 + 32 + tx * 4];
                kp[jj][0] = pk2(k0.x, k0.y); kp[jj][1] = pk2(k0.z, k0.w);
                kp[jj][2] = pk2(k1.x, k1.y); kp[jj][3] = pk2(k1.z, k1.w);
            }
#pragma unroll
            for (int i = 0; i < 8; i++) {
                float4 q = *(const float4*)&Qs[(ro + i) * 68 + d];
                u64 ap;
                ap = pk2(q.x, q.x);
                fma2(sacc2[i][0], ap, kp[0][0]); fma2(sacc2[i][1], ap, kp[0][1]);
                fma2(sacc2[i][2], ap, kp[0][2]); fma2(sacc2[i][3], ap, kp[0][3]);
                ap = pk2(q.y, q.y);
                fma2(sacc2[i][0], ap, kp[1][0]); fma2(sacc2[i][1], ap, kp[1][1]);
                fma2(sacc2[i][2], ap, kp[1][2]); fma2(sacc2[i][3], ap, kp[1][3]);
                ap = pk2(q.z, q.z);
                fma2(sacc2[i][0], ap, kp[2][0]); fma2(sacc2[i][1], ap, kp[2][1]);
                fma2(sacc2[i][2], ap, kp[2][2]); fma2(sacc2[i][3], ap, kp[2][3]);
                ap = pk2(q.w, q.w);
                fma2(sacc2[i][0], ap, kp[3][0]); fma2(sacc2[i][1], ap, kp[3][1]);
                fma2(sacc2[i][2], ap, kp[3][2]); fma2(sacc2[i][3], ap, kp[3][3]);
            }
        }

        // ---- online softmax per row (octet shfl reductions) ----
#pragma unroll
        for (int i = 0; i < 8; i++) {
            float f[8];
            upk2(sacc2[i][0], f[0], f[1]);
            upk2(sacc2[i][1], f[2], f[3]);
            upk2(sacc2[i][2], f[4], f[5]);
            upk2(sacc2[i][3], f[6], f[7]);
            float rmax = f[0];
#pragma unroll
            for (int j = 1; j < 8; j++) rmax = fmaxf(rmax, f[j]);
            rmax = fmaxf(rmax, __shfl_xor_sync(0xffffffffu, rmax, 1));
            rmax = fmaxf(rmax, __shfl_xor_sync(0xffffffffu, rmax, 2));
            rmax = fmaxf(rmax, __shfl_xor_sync(0xffffffffu, rmax, 4));
            float mn = fmaxf(mreg[i], rmax);
            float cc = __expf(mreg[i] - mn);
            mreg[i] = mn;
            float sum = 0.f;
#pragma unroll
            for (int j = 0; j < 8; j++) {
                f[j] = __expf(f[j] - mn);
                sum += f[j];
            }
            sum += __shfl_xor_sync(0xffffffffu, sum, 1);
            sum += __shfl_xor_sync(0xffffffffu, sum, 2);
            sum += __shfl_xor_sync(0xffffffffu, sum, 4);
            sreg[i] = sreg[i] * cc + sum;
            *(float4*)&Ps[(ro + i) * 68 + tx * 4] = make_float4(f[0], f[1], f[2], f[3]);
            *(float4*)&Ps[(ro + i) * 68 + 32 + tx * 4] = make_float4(f[4], f[5], f[6], f[7]);
            u64 cp = pk2(cc, cc);
#pragma unroll
            for (int j = 0; j < 4; j++) mul2(acc2[i][j], acc2[i][j], cp);
        }
        __syncwarp();   // P rows produced & consumed within the same octet

        // ---- PV : per t4, 8 V loads + 8 P broadcasts feed 256 MACs ----
#pragma unroll
        for (int t = 0; t < 64; t += 4) {
            u64 vp[4][4];
#pragma unroll
            for (int jj = 0; jj < 4; jj++) {
                float4 v0 = *(const float4*)&Vs[(t + jj) * 68 + tx * 4];
                float4 v1 = *(const float4*)&Vs[(t + jj) * 68 + 32 + tx * 4];
                vp[jj][0] = pk2(v0.x, v0.y); vp[jj][1] = pk2(v0.z, v0.w);
                vp[jj][2] = pk2(v1.x, v1.y); vp[jj][3] = pk2(v1.z, v1.w);
            }
#pragma unroll
            for (int i = 0; i < 8; i++) {
                float4 p = *(const float4*)&Ps[(ro + i) * 68 + t];
                u64 ap;
                ap = pk2(p.x, p.x);
                fma2(acc2[i][0], ap, vp[0][0]); fma2(acc2[i][1], ap, vp[0][1]);
                fma2(acc2[i][2], ap, vp[0][2]); fma2(acc2[i][3], ap, vp[0][3]);
                ap = pk2(p.y, p.y);
                fma2(acc2[i][0], ap, vp[1][0]); fma2(acc2[i][1], ap, vp[1][1]);
                fma2(acc2[i][2], ap, vp[1][2]); fma2(acc2[i][3], ap, vp[1][3]);
                ap = pk2(p.z, p.z);
                fma2(acc2[i][0], ap, vp[2][0]); fma2(acc2[i][1], ap, vp[2][1]);
                fma2(acc2[i][2], ap, vp[2][2]); fma2(acc2[i][3], ap, vp[2][3]);
                ap = pk2(p.w, p.w);
                fma2(acc2[i][0], ap, vp[3][0]); fma2(acc2[i][1], ap, vp[3][1]);
                fma2(acc2[i][2], ap, vp[3][2]); fma2(acc2[i][3], ap, vp[3][3]);
            }
        }
    }

    float* Og = g_o + (size_t)bh * (LSEQ * HDIM);
#pragma unroll
    for (int i = 0; i < 8; i++) {
        float inv = 1.0f / sreg[i];
        float f0, f1, f2, f3, f4, f5, f6, f7;
        upk2(acc2[i][0], f0, f1);
        upk2(acc2[i][1], f2, f3);
        upk2(acc2[i][2], f4, f5);
        upk2(acc2[i][3], f6, f7);
        *(float4*)(Og + (size_t)(r0 + ro + i) * HDIM + tx * 4) =
            make_float4(f0 * inv, f1 * inv, f2 * inv, f3 * inv);
        *(float4*)(Og + (size_t)(r0 + ro + i) * HDIM + 32 + tx * 4) =
            make_float4(f4 * inv, f5 * inv, f6 * inv, f7 * inv);
    }
    if (tx == 0) {
#pragma unroll
        for (int i = 0; i < 8; i++) {
            g_m[(size_t)bh * LSEQ + r0 + ro + i] = mreg[i];
            g_s[(size_t)bh * LSEQ + r0 + ro + i] = sreg[i];
        }
    }
}

// ---------------------------------------------------------------------------
// Attention-matrix writer (only when out_size includes attention):
// recompute S tilewise, apply stored (m, s), write [B,H,L,T] fp32.
// ---------------------------------------------------------------------------
__global__ __launch_bounds__(256) void attnout_kernel(float* __restrict__ att)
{
    __shared__ float Qs[SQS];
    __shared__ float Kt[SQS];
    __shared__ float mrow[64];
    __shared__ float sinv[64];

    const int tid = threadIdx.x;
    const int bh  = blockIdx.y;
    const int r0  = blockIdx.x * 64;

    const float* Qg = g_q + (size_t)bh * (LSEQ * HDIM);
    const float* Kg = g_k + (size_t)bh * (LSEQ * HDIM);

#pragma unroll
    for (int i = 0; i < 4; i++) {
        int idx = tid + i * 256;
        int r = idx >> 4;
        int d4 = (idx & 15) << 2;
        float4 q = *(const float4*)(Qg + (size_t)(r0 + r) * HDIM + d4);
        *(float4*)&Qs[r * 68 + d4] =
            make_float4(q.x * 0.125f, q.y * 0.125f, q.z * 0.125f, q.w * 0.125f);
    }
    if (tid < 64) {
        mrow[tid] = g_m[(size_t)bh * LSEQ + r0 + tid];
        sinv[tid] = 1.0f / g_s[(size_t)bh * LSEQ + r0 + tid];
    }

    const int ro = (tid >> 4) * 4;
    const int co = (tid & 15) * 4;

    for (int t0 = 0; t0 < LSEQ; t0 += 64) {
        __syncthreads();
#pragma unroll
        for (int i = 0; i < 4; i++) {
            int idx = tid + i * 256;
            int t = idx >> 4;
            int d4 = (idx & 15) << 2;
            float4 kv = *(const float4*)(Kg + (size_t)(t0 + t) * HDIM + d4);
            Kt[(d4 + 0) * 68 + t] = kv.x;
            Kt[(d4 + 1) * 68 + t] = kv.y;
            Kt[(d4 + 2) * 68 + t] = kv.z;
            Kt[(d4 + 3) * 68 + t] = kv.w;
        }
        __syncthreads();

        float sacc[4][4];
#pragma unroll
        for (int i = 0; i < 4; i++)
#pragma unroll
            for (int j = 0; j < 4; j++) sacc[i][j] = 0.f;
#pragma unroll
        for (int d = 0; d < 64; d += 4) {
            float4 q4[4], kv[4];
#pragma unroll
            for (int i = 0; i < 4; i++) q4[i] = *(const float4*)&Qs[(ro + i) * 68 + d];
#pragma unroll
            for (int jj = 0; jj < 4; jj++) kv[jj] = *(const float4*)&Kt[(d + jj) * 68 + co];
#pragma unroll
            for (int i = 0; i < 4; i++) {
                float qa[4] = {q4[i].x, q4[i].y, q4[i].z, q4[i].w};
#pragma unroll
                for (int jj = 0; jj < 4; jj++) {
                    sacc[i][0] += qa[jj] * kv[jj].x;
                    sacc[i][1] += qa[jj] * kv[jj].y;
                    sacc[i][2] += qa[jj] * kv[jj].z;
                    sacc[i][3] += qa[jj] * kv[jj].w;
                }
            }
        }
#pragma unroll
        for (int i = 0; i < 4; i++) {
            float mi = mrow[ro + i];
            float si = sinv[ro + i];
            float4 o = make_float4(__expf(sacc[i][0] - mi) * si,
                                   __expf(sacc[i][1] - mi) * si,
                                   __expf(sacc[i][2] - mi) * si,
                                   __expf(sacc[i][3] - mi) * si);
            *(float4*)(att + ((size_t)bh * LSEQ + r0 + ro + i) * LSEQ + t0 + co) = o;
        }
    }
}

// ---------------------------------------------------------------------------
extern "C" void kernel_launch(void* const* d_in, const int* in_sizes, int n_in,
                              void* d_out, int out_size)
{
    const float* query = (const float*)d_in[0];
    const float* key   = (const float*)d_in[1];
    const float* value = (const float*)d_in[2];
    const float* Wq    = (const float*)d_in[3];
    const float* Wk    = (const float*)d_in[4];
    const float* Wv    = (const float*)d_in[5];
    const float* Wo    = (const float*)d_in[6];
    const float* bo    = (const float*)d_in[7];
    float* out = (float*)d_out;

    float *qp, *kp, *vp, *op;
    cudaGetSymbolAddress((void**)&qp, g_q);
    cudaGetSymbolAddress((void**)&kp, g_k);
    cudaGetSymbolAddress((void**)&vp, g_v);
    cudaGetSymbolAddress((void**)&op, g_o);

    cudaFuncSetAttribute(gemm4, cudaFuncAttributeMaxDynamicSharedMemorySize, G_SMEM_B);
    dim3 gg(DMODEL / 128, M_TOT / 128);  // (8, 64)
    gemm4<<<gg, 128, G_SMEM_B>>>(query, Wq, nullptr, qp, 0, 1);
    gemm4<<<gg, 128, G_SMEM_B>>>(key,   Wk, nullptr, kp, 0, 1);
    gemm4<<<gg, 128, G_SMEM_B>>>(value, Wv, nullptr, vp, 0, 1);

    cudaFuncSetAttribute(flash4, cudaFuncAttributeMaxDynamicSharedMemorySize, FSHM);
    flash4<<<dim3(LSEQ / 128, NB * NH), 128, FSHM>>>();

    gemm4<<<gg, 128, G_SMEM_B>>>(op, Wo, bo, out, 1, 0);

    if (out_size > OUT_ELEMS) {
        attnout_kernel<<<dim3(LSEQ / 64, NB * NH), 256>>>(out + OUT_ELEMS);
    }
}